// round 1
// baseline (speedup 1.0000x reference)
#include <cuda_runtime.h>
#include <cuda_bf16.h>
#include <cstdint>

// ---------------------------------------------------------------------------
// GPT-1 forward: B=4, S=1024, D=768, H=12, HD=64, N_LAYER=5
// Baseline: fp32 SIMT tiled GEMMs + materialized attention scores.
// ---------------------------------------------------------------------------

#define NB 4
#define SS 1024
#define DD 768
#define HH 12
#define HDD 64
#define NLAYER 5
#define TOKENS (NB * SS)           // 4096
#define D3 (3 * DD)                // 2304
#define D4 (4 * DD)                // 3072

// -------------------- device scratch (no cudaMalloc allowed) ---------------
__device__ float g_h[TOKENS * DD];
__device__ float g_n[TOKENS * DD];
__device__ float g_tmp[TOKENS * DD];
__device__ float g_attn[TOKENS * DD];
__device__ float g_qkv[TOKENS * D3];
__device__ float g_fc[TOKENS * D4];
__device__ float g_scores[(size_t)NB * HH * SS * SS];   // 201 MB
__device__ int   g_is_i64;

// -------------------- helpers ----------------------------------------------
__device__ __forceinline__ float warp_sum(float v) {
    #pragma unroll
    for (int o = 16; o; o >>= 1) v += __shfl_xor_sync(0xffffffffu, v, o);
    return v;
}
__device__ __forceinline__ float warp_max(float v) {
    #pragma unroll
    for (int o = 16; o; o >>= 1) v = fmaxf(v, __shfl_xor_sync(0xffffffffu, v, o));
    return v;
}

__device__ __forceinline__ float gelu_f(float x) {
    const float c = 0.7978845608028654f;  // sqrt(2/pi)
    float t = tanhf(c * (x + 0.044715f * x * x * x));
    return 0.5f * x * (1.0f + t);
}

// -------------------- input_ids dtype detection ----------------------------
// If int64 (little-endian), every odd int32 word of the first 64 is zero
// (tokens < 40478 << 2^31). If int32, those are real tokens (all-zero prob ~0).
__global__ void detect_kernel(const int* __restrict__ ids) {
    int any = 0;
    for (int i = 1; i < 64; i += 2) any |= ids[i];
    g_is_i64 = (any == 0) ? 1 : 0;
}

// -------------------- embedding --------------------------------------------
__global__ void embed_kernel(const int* __restrict__ ids,
                             const float* __restrict__ tok,
                             const float* __restrict__ pos,
                             float* __restrict__ h) {
    int i = blockIdx.x * blockDim.x + threadIdx.x;
    if (i >= TOKENS * DD) return;
    int t = i / DD;
    int d = i - t * DD;
    int s = t & (SS - 1);
    int id = g_is_i64 ? ids[2 * t] : ids[t];
    h[i] = tok[(size_t)id * DD + d] + pos[(size_t)s * DD + d];
}

// -------------------- generic GEMM: C = A@B + bias (+ optional GELU) -------
// A: [M,K] lda, B: [K,N] ldb, C: [M,N] ldc. M%64==0, N%64==0, K%16==0.
// Block 256 threads = 16x16, each thread computes a 4x4 micro-tile.
__global__ void gemm_kernel(const float* __restrict__ A, int lda,
                            const float* __restrict__ B, int ldb,
                            const float* __restrict__ bias,
                            float* __restrict__ C, int ldc,
                            int K, int act) {
    __shared__ float As[16][64];
    __shared__ float Bs[16][64];
    int tid = threadIdx.x;
    int tx = tid & 15, ty = tid >> 4;
    int rowBase = blockIdx.y * 64;
    int colBase = blockIdx.x * 64;

    float acc[4][4] = {};

    for (int k0 = 0; k0 < K; k0 += 16) {
        #pragma unroll
        for (int i = 0; i < 4; i++) {
            int idx = tid + i * 256;
            int r = idx >> 4, kk = idx & 15;
            As[kk][r] = A[(size_t)(rowBase + r) * lda + k0 + kk];
        }
        #pragma unroll
        for (int i = 0; i < 4; i++) {
            int idx = tid + i * 256;
            int kk = idx >> 6, c = idx & 63;
            Bs[kk][c] = B[(size_t)(k0 + kk) * ldb + colBase + c];
        }
        __syncthreads();
        #pragma unroll
        for (int kk = 0; kk < 16; kk++) {
            float4 a4 = *(const float4*)&As[kk][ty * 4];
            float4 b4 = *(const float4*)&Bs[kk][tx * 4];
            float av[4] = {a4.x, a4.y, a4.z, a4.w};
            float bv[4] = {b4.x, b4.y, b4.z, b4.w};
            #pragma unroll
            for (int i = 0; i < 4; i++)
                #pragma unroll
                for (int j = 0; j < 4; j++)
                    acc[i][j] += av[i] * bv[j];
        }
        __syncthreads();
    }

    #pragma unroll
    for (int i = 0; i < 4; i++) {
        int r = rowBase + ty * 4 + i;
        #pragma unroll
        for (int j = 0; j < 4; j++) {
            int c = colBase + tx * 4 + j;
            float v = acc[i][j] + bias[c];
            if (act == 1) v = gelu_f(v);
            C[(size_t)r * ldc + c] = v;
        }
    }
}

// -------------------- attention scores: S = Q K^T * scale + masks ----------
// grid: (S/64 k-tiles, S/64 q-tiles, B*H)
__global__ void attn_scores_kernel(const float* __restrict__ qkv,
                                   const float* __restrict__ mask,
                                   float* __restrict__ scores) {
    __shared__ float Qs[16][64];
    __shared__ float Ks[16][64];
    int tid = threadIdx.x;
    int tx = tid & 15, ty = tid >> 4;
    int bh = blockIdx.z;
    int b = bh / HH, hh = bh - b * HH;
    int qBase = blockIdx.y * 64;
    int kBase = blockIdx.x * 64;

    const float* Qb = qkv + (size_t)b * SS * D3 + hh * HDD;
    const float* Kb = Qb + DD;

    float acc[4][4] = {};

    for (int d0 = 0; d0 < HDD; d0 += 16) {
        #pragma unroll
        for (int i = 0; i < 4; i++) {
            int idx = tid + i * 256;
            int r = idx >> 4, dk = idx & 15;
            Qs[dk][r] = Qb[(size_t)(qBase + r) * D3 + d0 + dk];
            Ks[dk][r] = Kb[(size_t)(kBase + r) * D3 + d0 + dk];
        }
        __syncthreads();
        #pragma unroll
        for (int kk = 0; kk < 16; kk++) {
            float4 a4 = *(const float4*)&Qs[kk][ty * 4];
            float4 b4 = *(const float4*)&Ks[kk][tx * 4];
            float av[4] = {a4.x, a4.y, a4.z, a4.w};
            float bv[4] = {b4.x, b4.y, b4.z, b4.w};
            #pragma unroll
            for (int i = 0; i < 4; i++)
                #pragma unroll
                for (int j = 0; j < 4; j++)
                    acc[i][j] += av[i] * bv[j];
        }
        __syncthreads();
    }

    float* srow = scores + (size_t)bh * SS * SS;
    #pragma unroll
    for (int i = 0; i < 4; i++) {
        int q = qBase + ty * 4 + i;
        #pragma unroll
        for (int j = 0; j < 4; j++) {
            int k = kBase + tx * 4 + j;
            float v = acc[i][j] * 0.125f;            // 1/sqrt(64)
            if (k > q) v = -1e4f;                    // causal: w*c + (-1e4)*(1-c)
            v += (1.0f - mask[b * SS + k]) * (-3.402823466e38f);
            srow[(size_t)q * SS + k] = v;
        }
    }
}

// -------------------- softmax over rows of 1024 ----------------------------
__global__ void softmax_kernel(float* __restrict__ scores) {
    float* row = scores + (size_t)blockIdx.x * SS;
    int tid = threadIdx.x;  // 256
    float4 v = ((float4*)row)[tid];

    __shared__ float sh[8];
    float m = fmaxf(fmaxf(v.x, v.y), fmaxf(v.z, v.w));
    m = warp_max(m);
    if ((tid & 31) == 0) sh[tid >> 5] = m;
    __syncthreads();
    float M = sh[0];
    #pragma unroll
    for (int i = 1; i < 8; i++) M = fmaxf(M, sh[i]);
    __syncthreads();

    v.x = __expf(v.x - M); v.y = __expf(v.y - M);
    v.z = __expf(v.z - M); v.w = __expf(v.w - M);
    float s = v.x + v.y + v.z + v.w;
    s = warp_sum(s);
    if ((tid & 31) == 0) sh[tid >> 5] = s;
    __syncthreads();
    float S = 0.f;
    #pragma unroll
    for (int i = 0; i < 8; i++) S += sh[i];
    float inv = 1.0f / S;
    v.x *= inv; v.y *= inv; v.z *= inv; v.w *= inv;
    ((float4*)row)[tid] = v;
}

// -------------------- PV: A = P @ V, written into [token, h*64+d] ----------
// grid: (1, S/64 q-tiles, B*H)
__global__ void attn_pv_kernel(const float* __restrict__ scores,
                               const float* __restrict__ qkv,
                               float* __restrict__ attn) {
    __shared__ float Ps[16][64];
    __shared__ float Vs[16][64];
    int tid = threadIdx.x;
    int tx = tid & 15, ty = tid >> 4;
    int bh = blockIdx.z;
    int b = bh / HH, hh = bh - b * HH;
    int qBase = blockIdx.y * 64;

    const float* P = scores + (size_t)bh * SS * SS;
    const float* Vb = qkv + (size_t)b * SS * D3 + 2 * DD + hh * HDD;

    float acc[4][4] = {};

    for (int k0 = 0; k0 < SS; k0 += 16) {
        #pragma unroll
        for (int i = 0; i < 4; i++) {
            int idx = tid + i * 256;
            int r = idx >> 4, kk = idx & 15;
            Ps[kk][r] = P[(size_t)(qBase + r) * SS + k0 + kk];
        }
        #pragma unroll
        for (int i = 0; i < 4; i++) {
            int idx = tid + i * 256;
            int kk = idx >> 6, c = idx & 63;
            Vs[kk][c] = Vb[(size_t)(k0 + kk) * D3 + c];
        }
        __syncthreads();
        #pragma unroll
        for (int kk = 0; kk < 16; kk++) {
            float4 a4 = *(const float4*)&Ps[kk][ty * 4];
            float4 b4 = *(const float4*)&Vs[kk][tx * 4];
            float av[4] = {a4.x, a4.y, a4.z, a4.w};
            float bv[4] = {b4.x, b4.y, b4.z, b4.w};
            #pragma unroll
            for (int i = 0; i < 4; i++)
                #pragma unroll
                for (int j = 0; j < 4; j++)
                    acc[i][j] += av[i] * bv[j];
        }
        __syncthreads();
    }

    #pragma unroll
    for (int i = 0; i < 4; i++) {
        int q = qBase + ty * 4 + i;
        #pragma unroll
        for (int j = 0; j < 4; j++) {
            int d = tx * 4 + j;
            attn[(size_t)(b * SS + q) * DD + hh * HDD + d] = acc[i][j];
        }
    }
}

// -------------------- fused residual-add + LayerNorm -----------------------
// out[row] = LN(x[row] + y[row]) * w + b ; one block (256 thr) per row of 768
__global__ void add_ln_kernel(const float* __restrict__ x,
                              const float* __restrict__ y,
                              const float* __restrict__ w,
                              const float* __restrict__ b,
                              float* __restrict__ out) {
    int row = blockIdx.x;
    const float* xr = x + (size_t)row * DD;
    const float* yr = y + (size_t)row * DD;
    int tid = threadIdx.x;

    float v0 = xr[tid] + yr[tid];
    float v1 = xr[tid + 256] + yr[tid + 256];
    float v2 = xr[tid + 512] + yr[tid + 512];

    __shared__ float sh[8];
    float s = warp_sum(v0 + v1 + v2);
    if ((tid & 31) == 0) sh[tid >> 5] = s;
    __syncthreads();
    float tot = 0.f;
    #pragma unroll
    for (int i = 0; i < 8; i++) tot += sh[i];
    float mu = tot * (1.0f / DD);
    __syncthreads();

    float d0 = v0 - mu, d1 = v1 - mu, d2 = v2 - mu;
    float s2 = warp_sum(d0 * d0 + d1 * d1 + d2 * d2);
    if ((tid & 31) == 0) sh[tid >> 5] = s2;
    __syncthreads();
    float tot2 = 0.f;
    #pragma unroll
    for (int i = 0; i < 8; i++) tot2 += sh[i];
    float r = rsqrtf(tot2 * (1.0f / DD) + 1e-5f);

    float* orow = out + (size_t)row * DD;
    orow[tid]       = d0 * r * w[tid]       + b[tid];
    orow[tid + 256] = d1 * r * w[tid + 256] + b[tid + 256];
    orow[tid + 512] = d2 * r * w[tid + 512] + b[tid + 512];
}

// ---------------------------------------------------------------------------
extern "C" void kernel_launch(void* const* d_in, const int* in_sizes, int n_in,
                              void* d_out, int out_size) {
    const int*   ids      = (const int*)  d_in[0];
    // d_in[1] = position_ids (== arange(S)), unused
    const float* mask     = (const float*)d_in[2];
    const float* tok_emb  = (const float*)d_in[3];
    const float* pos_emb  = (const float*)d_in[4];
    const float* c_attn_w = (const float*)d_in[5];
    const float* c_attn_b = (const float*)d_in[6];
    const float* c_proj_w = (const float*)d_in[7];
    const float* c_proj_b = (const float*)d_in[8];
    const float* ln1_w    = (const float*)d_in[9];
    const float* ln1_b    = (const float*)d_in[10];
    const float* c_fc_w   = (const float*)d_in[11];
    const float* c_fc_b   = (const float*)d_in[12];
    const float* mlp_w    = (const float*)d_in[13];
    const float* mlp_b    = (const float*)d_in[14];
    const float* ln2_w    = (const float*)d_in[15];
    const float* ln2_b    = (const float*)d_in[16];

    float *h, *n, *tmp, *attn, *qkv, *fc, *scores;
    cudaGetSymbolAddress((void**)&h,      g_h);
    cudaGetSymbolAddress((void**)&n,      g_n);
    cudaGetSymbolAddress((void**)&tmp,    g_tmp);
    cudaGetSymbolAddress((void**)&attn,   g_attn);
    cudaGetSymbolAddress((void**)&qkv,    g_qkv);
    cudaGetSymbolAddress((void**)&fc,     g_fc);
    cudaGetSymbolAddress((void**)&scores, g_scores);

    detect_kernel<<<1, 1>>>(ids);
    embed_kernel<<<(TOKENS * DD + 255) / 256, 256>>>(ids, tok_emb, pos_emb, h);

    for (int i = 0; i < NLAYER; i++) {
        // QKV projection: [4096,768] @ [768,2304]
        gemm_kernel<<<dim3(D3 / 64, TOKENS / 64), 256>>>(
            h, DD, c_attn_w + (size_t)i * DD * D3, D3,
            c_attn_b + (size_t)i * D3, qkv, D3, DD, 0);

        // scores = Q K^T * scale + causal + ext_mask
        attn_scores_kernel<<<dim3(SS / 64, SS / 64, NB * HH), 256>>>(qkv, mask, scores);

        // row softmax
        softmax_kernel<<<NB * HH * SS, 256>>>(scores);

        // A = P @ V
        attn_pv_kernel<<<dim3(1, SS / 64, NB * HH), 256>>>(scores, qkv, attn);

        // attn out projection: [4096,768] @ [768,768]
        gemm_kernel<<<dim3(DD / 64, TOKENS / 64), 256>>>(
            attn, DD, c_proj_w + (size_t)i * DD * DD, DD,
            c_proj_b + (size_t)i * DD, tmp, DD, DD, 0);

        // n = LN(h + attn_proj)
        add_ln_kernel<<<TOKENS, 256>>>(h, tmp, ln1_w + i * DD, ln1_b + i * DD, n);

        // fc = gelu(n @ c_fc_w + b): [4096,768] @ [768,3072]
        gemm_kernel<<<dim3(D4 / 64, TOKENS / 64), 256>>>(
            n, DD, c_fc_w + (size_t)i * DD * D4, D4,
            c_fc_b + (size_t)i * D4, fc, D4, DD, 1);

        // m = fc @ mlp_w + b: [4096,3072] @ [3072,768]
        gemm_kernel<<<dim3(DD / 64, TOKENS / 64), 256>>>(
            fc, D4, mlp_w + (size_t)i * D4 * DD, DD,
            mlp_b + (size_t)i * DD, tmp, DD, D4, 0);

        // h = LN(n + m)  (last layer writes straight to d_out)
        float* dst = (i == NLAYER - 1) ? (float*)d_out : h;
        add_ln_kernel<<<TOKENS, 256>>>(n, tmp, ln2_w + i * DD, ln2_b + i * DD, dst);
    }
}

// round 2
// speedup vs baseline: 3.1156x; 3.1156x over previous
#include <cuda_runtime.h>
#include <cuda_bf16.h>
#include <cstdint>

// ---------------------------------------------------------------------------
// GPT-1 forward: B=4, S=1024, D=768, H=12, HD=64, N_LAYER=5
// Round 2: all GEMMs (incl. QK^T and PV) via mma.sync tf32 tensor cores.
// ---------------------------------------------------------------------------

#define NB 4
#define SS 1024
#define DD 768
#define HH 12
#define HDD 64
#define NLAYER 5
#define TOKENS (NB * SS)           // 4096
#define D3 (3 * DD)                // 2304
#define D4 (4 * DD)                // 3072

// -------------------- device scratch (no cudaMalloc allowed) ---------------
__device__ float g_h[TOKENS * DD];
__device__ float g_n[TOKENS * DD];
__device__ float g_tmp[TOKENS * DD];
__device__ float g_attn[TOKENS * DD];
__device__ float g_qkv[TOKENS * D3];
__device__ float g_fc[TOKENS * D4];
__device__ float g_scores[(size_t)NB * HH * SS * SS];   // 201 MB
__device__ int   g_is_i64;

// -------------------- helpers ----------------------------------------------
__device__ __forceinline__ float warp_sum(float v) {
    #pragma unroll
    for (int o = 16; o; o >>= 1) v += __shfl_xor_sync(0xffffffffu, v, o);
    return v;
}
__device__ __forceinline__ float warp_max(float v) {
    #pragma unroll
    for (int o = 16; o; o >>= 1) v = fmaxf(v, __shfl_xor_sync(0xffffffffu, v, o));
    return v;
}
__device__ __forceinline__ float gelu_f(float x) {
    const float c = 0.7978845608028654f;  // sqrt(2/pi)
    float t = tanhf(c * (x + 0.044715f * x * x * x));
    return 0.5f * x * (1.0f + t);
}
__device__ __forceinline__ uint32_t to_tf32(float x) {
    uint32_t u;
    asm("cvt.rna.tf32.f32 %0, %1;" : "=r"(u) : "f"(x));
    return u;
}
__device__ __forceinline__ void mma8(float* c, const uint32_t* a, const uint32_t* b) {
    asm volatile(
        "mma.sync.aligned.m16n8k8.row.col.f32.tf32.tf32.f32 "
        "{%0,%1,%2,%3},{%4,%5,%6,%7},{%8,%9},{%0,%1,%2,%3};\n"
        : "+f"(c[0]), "+f"(c[1]), "+f"(c[2]), "+f"(c[3])
        : "r"(a[0]), "r"(a[1]), "r"(a[2]), "r"(a[3]), "r"(b[0]), "r"(b[1]));
}

// -------------------- input_ids dtype detection ----------------------------
__global__ void detect_kernel(const int* __restrict__ ids) {
    int any = 0;
    for (int i = 1; i < 64; i += 2) any |= ids[i];
    g_is_i64 = (any == 0) ? 1 : 0;
}

// -------------------- embedding --------------------------------------------
__global__ void embed_kernel(const int* __restrict__ ids,
                             const float* __restrict__ tok,
                             const float* __restrict__ pos,
                             float* __restrict__ h) {
    int i = blockIdx.x * blockDim.x + threadIdx.x;
    if (i >= TOKENS * DD) return;
    int t = i / DD;
    int d = i - t * DD;
    int s = t & (SS - 1);
    int id = g_is_i64 ? ids[2 * t] : ids[t];
    h[i] = tok[(size_t)id * DD + d] + pos[(size_t)s * DD + d];
}

// ---------------------------------------------------------------------------
// Unified tf32 tensor-core GEMM.
//   MODE 0: C = A@B + bias                     (NN)
//   MODE 1: C = gelu(A@B + bias)               (NN)
//   MODE 2: scores = scale*Q@K^T + causal+mask (NT, z = b*H+h, strided)
//   MODE 3: attn   = P@V                       (NN, z = b*H+h, strided)
// Block tile BMxBN, K-step 16, 8 warps, each warp WMxWN (m16n8k8 atoms).
// ---------------------------------------------------------------------------
template<int BM, int BN, int WM, int WN, int MODE>
__global__ __launch_bounds__(256)
void mma_gemm(const float* __restrict__ Ain, int lda,
              const float* __restrict__ Bin, int ldb,
              const float* __restrict__ bias_or_mask,
              float* __restrict__ Cout, int ldc,
              int K) {
    constexpr int BK = 16;
    constexpr bool TRANSB = (MODE == 2);
    constexpr int WARPS_N = BN / WN;
    constexpr int AM = WM / 16;          // m-atoms per warp
    constexpr int AN = WN / 8;           // n-atoms per warp
    constexpr int NA  = (BM * BK) / (4 * 256);   // float4 A loads / thread
    constexpr int NBt = (BN * BK) / (4 * 256);   // float4 B loads / thread
    constexpr int NBl = (NBt > 0) ? NBt : 1;

    __shared__ uint32_t As[2][BK][BM + 4];
    __shared__ uint32_t Bs[2][BK][BN + 4];

    const int tid  = threadIdx.x;
    const int wid  = tid >> 5;
    const int lane = tid & 31;
    const int g    = lane >> 2;   // group id (row-ish)
    const int tg   = lane & 3;    // thread in group (col-ish)
    const int warpM = (wid / WARPS_N) * WM;
    const int warpN = (wid % WARPS_N) * WN;
    const int rowBase = blockIdx.y * BM;
    const int colBase = blockIdx.x * BN;

    const float* A = Ain;
    const float* B = Bin;
    float* C = Cout;
    const float* bm = bias_or_mask;
    int b = 0;
    if (MODE == 2 || MODE == 3) {
        int z = blockIdx.z;
        b = z / HH;
        int h = z - b * HH;
        if (MODE == 2) {
            A = Ain + (size_t)b * SS * D3 + h * HDD;            // Q
            B = Ain + (size_t)b * SS * D3 + DD + h * HDD;       // K
            C = Cout + (size_t)z * SS * SS;
        } else {
            A = Ain + (size_t)z * SS * SS;                      // P
            B = Bin + (size_t)b * SS * D3 + 2 * DD + h * HDD;   // V
            C = Cout + (size_t)b * SS * DD + h * HDD;
        }
    }

    float acc[AM][AN][4];
    #pragma unroll
    for (int i = 0; i < AM; i++)
        #pragma unroll
        for (int j = 0; j < AN; j++)
            #pragma unroll
            for (int q = 0; q < 4; q++) acc[i][j][q] = 0.0f;

    float4 aS[NA];
    float4 bS[NBl];

    auto stageT = [&](int kt) {
        int k0 = kt * BK;
        #pragma unroll
        for (int it = 0; it < NA; it++) {
            int idx = tid + it * 256;
            int r = idx >> 2, kq = idx & 3;
            aS[it] = *reinterpret_cast<const float4*>(
                A + (size_t)(rowBase + r) * lda + k0 + kq * 4);
        }
        #pragma unroll
        for (int it = 0; it < NBl; it++) {
            int idx = tid + it * 256;
            if (TRANSB) {
                int r = idx >> 2, kq = idx & 3;
                bS[it] = *reinterpret_cast<const float4*>(
                    B + (size_t)(colBase + r) * ldb + k0 + kq * 4);
            } else {
                constexpr int BPR = BN / 4;
                int kr = idx / BPR, nq = idx % BPR;
                bS[it] = *reinterpret_cast<const float4*>(
                    B + (size_t)(k0 + kr) * ldb + colBase + nq * 4);
            }
        }
    };

    auto commitT = [&](int bw) {
        #pragma unroll
        for (int it = 0; it < NA; it++) {
            int idx = tid + it * 256;
            int r = idx >> 2, kq = idx & 3;
            const float* v = reinterpret_cast<const float*>(&aS[it]);
            #pragma unroll
            for (int c = 0; c < 4; c++) As[bw][kq * 4 + c][r] = to_tf32(v[c]);
        }
        #pragma unroll
        for (int it = 0; it < NBl; it++) {
            int idx = tid + it * 256;
            const float* v = reinterpret_cast<const float*>(&bS[it]);
            if (TRANSB) {
                int r = idx >> 2, kq = idx & 3;
                #pragma unroll
                for (int c = 0; c < 4; c++) Bs[bw][kq * 4 + c][r] = to_tf32(v[c]);
            } else {
                constexpr int BPR = BN / 4;
                int kr = idx / BPR, nq = idx % BPR;
                #pragma unroll
                for (int c = 0; c < 4; c++) Bs[bw][kr][nq * 4 + c] = to_tf32(v[c]);
            }
        }
    };

    stageT(0);
    commitT(0);
    __syncthreads();

    int buf = 0;
    const int KT = K / BK;
    for (int kt = 0; kt < KT; kt++) {
        bool more = (kt + 1 < KT);
        if (more) stageT(kt + 1);

        #pragma unroll
        for (int kk = 0; kk < BK; kk += 8) {
            uint32_t af[AM][4];
            #pragma unroll
            for (int i = 0; i < AM; i++) {
                int m = warpM + i * 16 + g;
                af[i][0] = As[buf][kk + tg][m];
                af[i][1] = As[buf][kk + tg][m + 8];
                af[i][2] = As[buf][kk + tg + 4][m];
                af[i][3] = As[buf][kk + tg + 4][m + 8];
            }
            uint32_t bf[AN][2];
            #pragma unroll
            for (int j = 0; j < AN; j++) {
                int n = warpN + j * 8 + g;
                bf[j][0] = Bs[buf][kk + tg][n];
                bf[j][1] = Bs[buf][kk + tg + 4][n];
            }
            #pragma unroll
            for (int i = 0; i < AM; i++)
                #pragma unroll
                for (int j = 0; j < AN; j++)
                    mma8(acc[i][j], af[i], bf[j]);
        }

        if (more) {
            commitT(buf ^ 1);
            __syncthreads();
        }
        buf ^= 1;
    }

    // ---- epilogue ----
    #pragma unroll
    for (int i = 0; i < AM; i++) {
        int r0 = rowBase + warpM + i * 16 + g;
        int r1 = r0 + 8;
        #pragma unroll
        for (int j = 0; j < AN; j++) {
            int c = colBase + warpN + j * 8 + tg * 2;
            float v0 = acc[i][j][0], v1 = acc[i][j][1];
            float v2 = acc[i][j][2], v3 = acc[i][j][3];
            if (MODE == 0 || MODE == 1) {
                float bb0 = bm[c], bb1 = bm[c + 1];
                v0 += bb0; v1 += bb1; v2 += bb0; v3 += bb1;
                if (MODE == 1) {
                    v0 = gelu_f(v0); v1 = gelu_f(v1);
                    v2 = gelu_f(v2); v3 = gelu_f(v3);
                }
            } else if (MODE == 2) {
                float m0 = (1.0f - bm[b * SS + c])     * (-3.402823466e38f);
                float m1 = (1.0f - bm[b * SS + c + 1]) * (-3.402823466e38f);
                v0 *= 0.125f; v1 *= 0.125f; v2 *= 0.125f; v3 *= 0.125f;
                if (c > r0)     v0 = -1e4f;
                if (c + 1 > r0) v1 = -1e4f;
                if (c > r1)     v2 = -1e4f;
                if (c + 1 > r1) v3 = -1e4f;
                v0 += m0; v1 += m1; v2 += m0; v3 += m1;
            }
            *reinterpret_cast<float2*>(C + (size_t)r0 * ldc + c) = make_float2(v0, v1);
            *reinterpret_cast<float2*>(C + (size_t)r1 * ldc + c) = make_float2(v2, v3);
        }
    }
}

// -------------------- softmax over rows of 1024 ----------------------------
__global__ void softmax_kernel(float* __restrict__ scores) {
    float* row = scores + (size_t)blockIdx.x * SS;
    int tid = threadIdx.x;  // 256
    float4 v = ((float4*)row)[tid];

    __shared__ float sh[8];
    float m = fmaxf(fmaxf(v.x, v.y), fmaxf(v.z, v.w));
    m = warp_max(m);
    if ((tid & 31) == 0) sh[tid >> 5] = m;
    __syncthreads();
    float M = sh[0];
    #pragma unroll
    for (int i = 1; i < 8; i++) M = fmaxf(M, sh[i]);
    __syncthreads();

    v.x = __expf(v.x - M); v.y = __expf(v.y - M);
    v.z = __expf(v.z - M); v.w = __expf(v.w - M);
    float s = v.x + v.y + v.z + v.w;
    s = warp_sum(s);
    if ((tid & 31) == 0) sh[tid >> 5] = s;
    __syncthreads();
    float S = 0.f;
    #pragma unroll
    for (int i = 0; i < 8; i++) S += sh[i];
    float inv = 1.0f / S;
    v.x *= inv; v.y *= inv; v.z *= inv; v.w *= inv;
    ((float4*)row)[tid] = v;
}

// -------------------- fused residual-add + LayerNorm -----------------------
__global__ void add_ln_kernel(const float* __restrict__ x,
                              const float* __restrict__ y,
                              const float* __restrict__ w,
                              const float* __restrict__ b,
                              float* __restrict__ out) {
    int row = blockIdx.x;
    const float* xr = x + (size_t)row * DD;
    const float* yr = y + (size_t)row * DD;
    int tid = threadIdx.x;

    float v0 = xr[tid] + yr[tid];
    float v1 = xr[tid + 256] + yr[tid + 256];
    float v2 = xr[tid + 512] + yr[tid + 512];

    __shared__ float sh[8];
    float s = warp_sum(v0 + v1 + v2);
    if ((tid & 31) == 0) sh[tid >> 5] = s;
    __syncthreads();
    float tot = 0.f;
    #pragma unroll
    for (int i = 0; i < 8; i++) tot += sh[i];
    float mu = tot * (1.0f / DD);
    __syncthreads();

    float d0 = v0 - mu, d1 = v1 - mu, d2 = v2 - mu;
    float s2 = warp_sum(d0 * d0 + d1 * d1 + d2 * d2);
    if ((tid & 31) == 0) sh[tid >> 5] = s2;
    __syncthreads();
    float tot2 = 0.f;
    #pragma unroll
    for (int i = 0; i < 8; i++) tot2 += sh[i];
    float r = rsqrtf(tot2 * (1.0f / DD) + 1e-5f);

    float* orow = out + (size_t)row * DD;
    orow[tid]       = d0 * r * w[tid]       + b[tid];
    orow[tid + 256] = d1 * r * w[tid + 256] + b[tid + 256];
    orow[tid + 512] = d2 * r * w[tid + 512] + b[tid + 512];
}

// ---------------------------------------------------------------------------
extern "C" void kernel_launch(void* const* d_in, const int* in_sizes, int n_in,
                              void* d_out, int out_size) {
    const int*   ids      = (const int*)  d_in[0];
    const float* mask     = (const float*)d_in[2];
    const float* tok_emb  = (const float*)d_in[3];
    const float* pos_emb  = (const float*)d_in[4];
    const float* c_attn_w = (const float*)d_in[5];
    const float* c_attn_b = (const float*)d_in[6];
    const float* c_proj_w = (const float*)d_in[7];
    const float* c_proj_b = (const float*)d_in[8];
    const float* ln1_w    = (const float*)d_in[9];
    const float* ln1_b    = (const float*)d_in[10];
    const float* c_fc_w   = (const float*)d_in[11];
    const float* c_fc_b   = (const float*)d_in[12];
    const float* mlp_w    = (const float*)d_in[13];
    const float* mlp_b    = (const float*)d_in[14];
    const float* ln2_w    = (const float*)d_in[15];
    const float* ln2_b    = (const float*)d_in[16];

    float *h, *n, *tmp, *attn, *qkv, *fc, *scores;
    cudaGetSymbolAddress((void**)&h,      g_h);
    cudaGetSymbolAddress((void**)&n,      g_n);
    cudaGetSymbolAddress((void**)&tmp,    g_tmp);
    cudaGetSymbolAddress((void**)&attn,   g_attn);
    cudaGetSymbolAddress((void**)&qkv,    g_qkv);
    cudaGetSymbolAddress((void**)&fc,     g_fc);
    cudaGetSymbolAddress((void**)&scores, g_scores);

    detect_kernel<<<1, 1>>>(ids);
    embed_kernel<<<(TOKENS * DD + 255) / 256, 256>>>(ids, tok_emb, pos_emb, h);

    for (int i = 0; i < NLAYER; i++) {
        // QKV: [4096,768] @ [768,2304]
        mma_gemm<128, 128, 64, 32, 0><<<dim3(D3 / 128, TOKENS / 128), 256>>>(
            h, DD, c_attn_w + (size_t)i * DD * D3, D3,
            c_attn_b + (size_t)i * D3, qkv, D3, DD);

        // scores = scale * Q K^T + causal + ext mask
        mma_gemm<128, 128, 64, 32, 2><<<dim3(SS / 128, SS / 128, NB * HH), 256>>>(
            qkv, D3, qkv, D3, mask, scores, SS, HDD);

        // row softmax
        softmax_kernel<<<NB * HH * SS, 256>>>(scores);

        // A = P @ V
        mma_gemm<128, 64, 32, 32, 3><<<dim3(1, SS / 128, NB * HH), 256>>>(
            scores, SS, qkv, D3, nullptr, attn, DD, SS);

        // attn out projection: [4096,768] @ [768,768]
        mma_gemm<128, 128, 64, 32, 0><<<dim3(DD / 128, TOKENS / 128), 256>>>(
            attn, DD, c_proj_w + (size_t)i * DD * DD, DD,
            c_proj_b + (size_t)i * DD, tmp, DD, DD);

        // n = LN(h + attn_proj)
        add_ln_kernel<<<TOKENS, 256>>>(h, tmp, ln1_w + i * DD, ln1_b + i * DD, n);

        // fc = gelu(n @ c_fc_w + b): [4096,768] @ [768,3072]
        mma_gemm<128, 128, 64, 32, 1><<<dim3(D4 / 128, TOKENS / 128), 256>>>(
            n, DD, c_fc_w + (size_t)i * DD * D4, D4,
            c_fc_b + (size_t)i * D4, fc, D4, DD);

        // m = fc @ mlp_w + b: [4096,3072] @ [3072,768]
        mma_gemm<128, 128, 64, 32, 0><<<dim3(DD / 128, TOKENS / 128), 256>>>(
            fc, D4, mlp_w + (size_t)i * D4 * DD, DD,
            mlp_b + (size_t)i * DD, tmp, DD, D4);

        // h = LN(n + m)  (last layer writes straight to d_out)
        float* dst = (i == NLAYER - 1) ? (float*)d_out : h;
        add_ln_kernel<<<TOKENS, 256>>>(n, tmp, ln2_w + i * DD, ln2_b + i * DD, dst);
    }
}

// round 3
// speedup vs baseline: 3.5841x; 1.1504x over previous
#include <cuda_runtime.h>
#include <cuda_bf16.h>
#include <cstdint>

// ---------------------------------------------------------------------------
// GPT-1 forward: B=4, S=1024, D=768, H=12, HD=64, N_LAYER=5
// Round 3: dense GEMMs via mma.sync tf32; attention fully fused (flash).
// ---------------------------------------------------------------------------

#define NB 4
#define SS 1024
#define DD 768
#define HH 12
#define HDD 64
#define NLAYER 5
#define TOKENS (NB * SS)           // 4096
#define D3 (3 * DD)                // 2304
#define D4 (4 * DD)                // 3072

// -------------------- device scratch (no cudaMalloc allowed) ---------------
__device__ float g_h[TOKENS * DD];
__device__ float g_n[TOKENS * DD];
__device__ float g_tmp[TOKENS * DD];
__device__ float g_attn[TOKENS * DD];
__device__ float g_qkv[TOKENS * D3];
__device__ float g_fc[TOKENS * D4];
__device__ int   g_is_i64;

// -------------------- helpers ----------------------------------------------
__device__ __forceinline__ float warp_sum(float v) {
    #pragma unroll
    for (int o = 16; o; o >>= 1) v += __shfl_xor_sync(0xffffffffu, v, o);
    return v;
}
__device__ __forceinline__ float gelu_f(float x) {
    const float c = 0.7978845608028654f;  // sqrt(2/pi)
    float t = tanhf(c * (x + 0.044715f * x * x * x));
    return 0.5f * x * (1.0f + t);
}
__device__ __forceinline__ uint32_t to_tf32(float x) {
    uint32_t u;
    asm("cvt.rna.tf32.f32 %0, %1;" : "=r"(u) : "f"(x));
    return u;
}
__device__ __forceinline__ float to_tf32f(float x) {
    return __uint_as_float(to_tf32(x));
}
__device__ __forceinline__ void mma8(float* c, const uint32_t* a, const uint32_t* b) {
    asm volatile(
        "mma.sync.aligned.m16n8k8.row.col.f32.tf32.tf32.f32 "
        "{%0,%1,%2,%3},{%4,%5,%6,%7},{%8,%9},{%0,%1,%2,%3};\n"
        : "+f"(c[0]), "+f"(c[1]), "+f"(c[2]), "+f"(c[3])
        : "r"(a[0]), "r"(a[1]), "r"(a[2]), "r"(a[3]), "r"(b[0]), "r"(b[1]));
}

// -------------------- input_ids dtype detection ----------------------------
__global__ void detect_kernel(const int* __restrict__ ids) {
    int any = 0;
    for (int i = 1; i < 64; i += 2) any |= ids[i];
    g_is_i64 = (any == 0) ? 1 : 0;
}

// -------------------- embedding --------------------------------------------
__global__ void embed_kernel(const int* __restrict__ ids,
                             const float* __restrict__ tok,
                             const float* __restrict__ pos,
                             float* __restrict__ h) {
    int i = blockIdx.x * blockDim.x + threadIdx.x;
    if (i >= TOKENS * DD) return;
    int t = i / DD;
    int d = i - t * DD;
    int s = t & (SS - 1);
    int id = g_is_i64 ? ids[2 * t] : ids[t];
    h[i] = tok[(size_t)id * DD + d] + pos[(size_t)s * DD + d];
}

// ---------------------------------------------------------------------------
// Dense tf32 tensor-core GEMM (NN).  MODE 0: +bias.  MODE 1: gelu(+bias).
// Block 128x128, K-step 16, 8 warps of 64x32, m16n8k8 atoms.
// ---------------------------------------------------------------------------
template<int BM, int BN, int WM, int WN, int MODE>
__global__ __launch_bounds__(256)
void mma_gemm(const float* __restrict__ A, int lda,
              const float* __restrict__ B, int ldb,
              const float* __restrict__ bias,
              float* __restrict__ C, int ldc,
              int K) {
    constexpr int BK = 16;
    constexpr int WARPS_N = BN / WN;
    constexpr int AM = WM / 16;
    constexpr int AN = WN / 8;
    constexpr int NA  = (BM * BK) / (4 * 256);
    constexpr int NBt = (BN * BK) / (4 * 256);

    __shared__ uint32_t As[2][BK][BM + 4];
    __shared__ uint32_t Bs[2][BK][BN + 4];

    const int tid  = threadIdx.x;
    const int wid  = tid >> 5;
    const int lane = tid & 31;
    const int g    = lane >> 2;
    const int tg   = lane & 3;
    const int warpM = (wid / WARPS_N) * WM;
    const int warpN = (wid % WARPS_N) * WN;
    const int rowBase = blockIdx.y * BM;
    const int colBase = blockIdx.x * BN;

    float acc[AM][AN][4];
    #pragma unroll
    for (int i = 0; i < AM; i++)
        #pragma unroll
        for (int j = 0; j < AN; j++)
            #pragma unroll
            for (int q = 0; q < 4; q++) acc[i][j][q] = 0.0f;

    float4 aS[NA];
    float4 bS[NBt];

    auto stageT = [&](int kt) {
        int k0 = kt * BK;
        #pragma unroll
        for (int it = 0; it < NA; it++) {
            int idx = tid + it * 256;
            int r = idx >> 2, kq = idx & 3;
            aS[it] = *reinterpret_cast<const float4*>(
                A + (size_t)(rowBase + r) * lda + k0 + kq * 4);
        }
        #pragma unroll
        for (int it = 0; it < NBt; it++) {
            int idx = tid + it * 256;
            constexpr int BPR = BN / 4;
            int kr = idx / BPR, nq = idx % BPR;
            bS[it] = *reinterpret_cast<const float4*>(
                B + (size_t)(k0 + kr) * ldb + colBase + nq * 4);
        }
    };

    auto commitT = [&](int bw) {
        #pragma unroll
        for (int it = 0; it < NA; it++) {
            int idx = tid + it * 256;
            int r = idx >> 2, kq = idx & 3;
            const float* v = reinterpret_cast<const float*>(&aS[it]);
            #pragma unroll
            for (int c = 0; c < 4; c++) As[bw][kq * 4 + c][r] = to_tf32(v[c]);
        }
        #pragma unroll
        for (int it = 0; it < NBt; it++) {
            int idx = tid + it * 256;
            const float* v = reinterpret_cast<const float*>(&bS[it]);
            constexpr int BPR = BN / 4;
            int kr = idx / BPR, nq = idx % BPR;
            #pragma unroll
            for (int c = 0; c < 4; c++) Bs[bw][kr][nq * 4 + c] = to_tf32(v[c]);
        }
    };

    stageT(0);
    commitT(0);
    __syncthreads();

    int buf = 0;
    const int KT = K / BK;
    for (int kt = 0; kt < KT; kt++) {
        bool more = (kt + 1 < KT);
        if (more) stageT(kt + 1);

        #pragma unroll
        for (int kk = 0; kk < BK; kk += 8) {
            uint32_t af[AM][4];
            #pragma unroll
            for (int i = 0; i < AM; i++) {
                int m = warpM + i * 16 + g;
                af[i][0] = As[buf][kk + tg][m];
                af[i][1] = As[buf][kk + tg][m + 8];
                af[i][2] = As[buf][kk + tg + 4][m];
                af[i][3] = As[buf][kk + tg + 4][m + 8];
            }
            uint32_t bf[AN][2];
            #pragma unroll
            for (int j = 0; j < AN; j++) {
                int n = warpN + j * 8 + g;
                bf[j][0] = Bs[buf][kk + tg][n];
                bf[j][1] = Bs[buf][kk + tg + 4][n];
            }
            #pragma unroll
            for (int i = 0; i < AM; i++)
                #pragma unroll
                for (int j = 0; j < AN; j++)
                    mma8(acc[i][j], af[i], bf[j]);
        }

        if (more) {
            commitT(buf ^ 1);
            __syncthreads();
        }
        buf ^= 1;
    }

    #pragma unroll
    for (int i = 0; i < AM; i++) {
        int r0 = rowBase + warpM + i * 16 + g;
        int r1 = r0 + 8;
        #pragma unroll
        for (int j = 0; j < AN; j++) {
            int c = colBase + warpN + j * 8 + tg * 2;
            float bb0 = bias[c], bb1 = bias[c + 1];
            float v0 = acc[i][j][0] + bb0, v1 = acc[i][j][1] + bb1;
            float v2 = acc[i][j][2] + bb0, v3 = acc[i][j][3] + bb1;
            if (MODE == 1) {
                v0 = gelu_f(v0); v1 = gelu_f(v1);
                v2 = gelu_f(v2); v3 = gelu_f(v3);
            }
            *reinterpret_cast<float2*>(C + (size_t)r0 * ldc + c) = make_float2(v0, v1);
            *reinterpret_cast<float2*>(C + (size_t)r1 * ldc + c) = make_float2(v2, v3);
        }
    }
}

// ---------------------------------------------------------------------------
// Fused flash attention (causal, GPT-1 semantics).
// Block: 128 q-rows, 4 warps (32 q-rows each, AM=2). K-blocks of 64 tokens.
// Per warp: S-frags via QK^T mma, online softmax in registers,
// P C-frag -> A-frag via intra-quad shuffles, PV mma accumulates O.
// Masked scores use -1e4 (matches reference: w*c + (-1e4)*(1-c)), then
// extended mask added.
// ---------------------------------------------------------------------------
#define QSTR 132   // Qs row stride (128+4)
#define KSTR 68    // Ks/Vs row stride (64+4)

__global__ __launch_bounds__(128)
void flash_kernel(const float* __restrict__ qkv,
                  const float* __restrict__ mask,
                  float* __restrict__ attn) {
    extern __shared__ float sm[];
    float* Qs  = sm;                        // [64][132] tf32
    float* Ks  = Qs + 64 * QSTR;            // [64][68]  tf32 (d-major)
    float* Vs  = Ks + 64 * KSTR;            // [64][68]  tf32 (token-major)
    float* Ems = Vs + 64 * KSTR;            // [64] extended-mask add

    const int tid  = threadIdx.x;
    const int wid  = tid >> 5;
    const int lane = tid & 31;
    const int g    = lane >> 2;
    const int tg   = lane & 3;
    const int warpM = wid * 32;
    const int qBase = blockIdx.x * 128;
    const int bh = blockIdx.y;
    const int b = bh / HH, h = bh - b * HH;

    const float* Qg = qkv + (size_t)b * SS * D3 + h * HDD;
    const float* Kg = Qg + DD;
    const float* Vg = Qg + 2 * DD;

    // ---- load Q tile (128x64) -> Qs[d][r], tf32 ----
    #pragma unroll
    for (int i = 0; i < 16; i++) {
        int idx = i * 128 + tid;
        int r = idx >> 4, dq = idx & 15;
        float4 v = *reinterpret_cast<const float4*>(
            Qg + (size_t)(qBase + r) * D3 + dq * 4);
        Qs[(dq * 4 + 0) * QSTR + r] = to_tf32f(v.x);
        Qs[(dq * 4 + 1) * QSTR + r] = to_tf32f(v.y);
        Qs[(dq * 4 + 2) * QSTR + r] = to_tf32f(v.z);
        Qs[(dq * 4 + 3) * QSTR + r] = to_tf32f(v.w);
    }

    float o[2][8][4];
    #pragma unroll
    for (int i = 0; i < 2; i++)
        #pragma unroll
        for (int j = 0; j < 8; j++)
            #pragma unroll
            for (int q = 0; q < 4; q++) o[i][j][q] = 0.0f;
    float mrow[2][2] = {{-1e30f, -1e30f}, {-1e30f, -1e30f}};
    float lrow[2][2] = {{0.f, 0.f}, {0.f, 0.f}};

    const int row[2][2] = {{qBase + warpM + g,      qBase + warpM + g + 8},
                           {qBase + warpM + 16 + g, qBase + warpM + 24 + g}};
    const int srcA = (lane & 28) | (tg >> 1);
    const int srcB = srcA | 2;
    const int e1   = tg & 1;

    const int nkb = qBase / 64 + 2;
    for (int kb = 0; kb < nkb; kb++) {
        __syncthreads();
        // ---- load K (d-major) and V (token-major) tiles, tf32 ----
        #pragma unroll
        for (int i = 0; i < 8; i++) {
            int idx = i * 128 + tid;
            int kt = idx >> 4, dq = idx & 15;
            size_t grow = (size_t)(b * SS + kb * 64 + kt) * D3;
            float4 kv = *reinterpret_cast<const float4*>(Kg + grow - (size_t)b * SS * D3 * 0 + (size_t)(kb * 64 + kt) * D3 * 0 + 0);
            kv = *reinterpret_cast<const float4*>(
                Kg + (size_t)(kb * 64 + kt) * D3 + dq * 4);
            Ks[(dq * 4 + 0) * KSTR + kt] = to_tf32f(kv.x);
            Ks[(dq * 4 + 1) * KSTR + kt] = to_tf32f(kv.y);
            Ks[(dq * 4 + 2) * KSTR + kt] = to_tf32f(kv.z);
            Ks[(dq * 4 + 3) * KSTR + kt] = to_tf32f(kv.w);
            float4 vv = *reinterpret_cast<const float4*>(
                Vg + (size_t)(kb * 64 + kt) * D3 + dq * 4);
            Vs[kt * KSTR + dq * 4 + 0] = to_tf32f(vv.x);
            Vs[kt * KSTR + dq * 4 + 1] = to_tf32f(vv.y);
            Vs[kt * KSTR + dq * 4 + 2] = to_tf32f(vv.z);
            Vs[kt * KSTR + dq * 4 + 3] = to_tf32f(vv.w);
        }
        if (tid < 64)
            Ems[tid] = (1.0f - mask[b * SS + kb * 64 + tid]) * (-3.402823466e38f);
        __syncthreads();

        // ---- S = Q @ K^T (16x64 per m-atom) ----
        float s[2][8][4];
        #pragma unroll
        for (int i = 0; i < 2; i++)
            #pragma unroll
            for (int j = 0; j < 8; j++)
                #pragma unroll
                for (int q = 0; q < 4; q++) s[i][j][q] = 0.0f;

        #pragma unroll
        for (int kk = 0; kk < 8; kk++) {
            int kr = kk * 8;
            uint32_t af[2][4];
            #pragma unroll
            for (int i = 0; i < 2; i++) {
                int m = warpM + i * 16 + g;
                af[i][0] = __float_as_uint(Qs[(kr + tg) * QSTR + m]);
                af[i][1] = __float_as_uint(Qs[(kr + tg) * QSTR + m + 8]);
                af[i][2] = __float_as_uint(Qs[(kr + tg + 4) * QSTR + m]);
                af[i][3] = __float_as_uint(Qs[(kr + tg + 4) * QSTR + m + 8]);
            }
            #pragma unroll
            for (int j = 0; j < 8; j++) {
                uint32_t bf[2];
                bf[0] = __float_as_uint(Ks[(kr + tg) * KSTR + j * 8 + g]);
                bf[1] = __float_as_uint(Ks[(kr + tg + 4) * KSTR + j * 8 + g]);
                mma8(s[0][j], af[0], bf);
                mma8(s[1][j], af[1], bf);
            }
        }

        // ---- scale + causal + ext mask, online softmax ----
        #pragma unroll
        for (int i = 0; i < 2; i++) {
            float mx0 = -1e30f, mx1 = -1e30f;
            #pragma unroll
            for (int j = 0; j < 8; j++) {
                int c0 = kb * 64 + j * 8 + tg * 2;
                float em0 = Ems[j * 8 + tg * 2];
                float em1 = Ems[j * 8 + tg * 2 + 1];
                float v0 = s[i][j][0] * 0.125f;
                float v1 = s[i][j][1] * 0.125f;
                float v2 = s[i][j][2] * 0.125f;
                float v3 = s[i][j][3] * 0.125f;
                if (c0 > row[i][0])     v0 = -1e4f;
                if (c0 + 1 > row[i][0]) v1 = -1e4f;
                if (c0 > row[i][1])     v2 = -1e4f;
                if (c0 + 1 > row[i][1]) v3 = -1e4f;
                v0 += em0; v1 += em1; v2 += em0; v3 += em1;
                s[i][j][0] = v0; s[i][j][1] = v1;
                s[i][j][2] = v2; s[i][j][3] = v3;
                mx0 = fmaxf(mx0, fmaxf(v0, v1));
                mx1 = fmaxf(mx1, fmaxf(v2, v3));
            }
            mx0 = fmaxf(mx0, __shfl_xor_sync(0xffffffffu, mx0, 1));
            mx0 = fmaxf(mx0, __shfl_xor_sync(0xffffffffu, mx0, 2));
            mx1 = fmaxf(mx1, __shfl_xor_sync(0xffffffffu, mx1, 1));
            mx1 = fmaxf(mx1, __shfl_xor_sync(0xffffffffu, mx1, 2));

            float mn0 = fmaxf(mrow[i][0], mx0);
            float mn1 = fmaxf(mrow[i][1], mx1);
            float al0 = __expf(mrow[i][0] - mn0);
            float al1 = __expf(mrow[i][1] - mn1);
            mrow[i][0] = mn0; mrow[i][1] = mn1;

            float sum0 = 0.f, sum1 = 0.f;
            #pragma unroll
            for (int j = 0; j < 8; j++) {
                float p0 = __expf(s[i][j][0] - mn0);
                float p1 = __expf(s[i][j][1] - mn0);
                float p2 = __expf(s[i][j][2] - mn1);
                float p3 = __expf(s[i][j][3] - mn1);
                s[i][j][0] = p0; s[i][j][1] = p1;
                s[i][j][2] = p2; s[i][j][3] = p3;
                sum0 += p0 + p1; sum1 += p2 + p3;
            }
            sum0 += __shfl_xor_sync(0xffffffffu, sum0, 1);
            sum0 += __shfl_xor_sync(0xffffffffu, sum0, 2);
            sum1 += __shfl_xor_sync(0xffffffffu, sum1, 1);
            sum1 += __shfl_xor_sync(0xffffffffu, sum1, 2);
            lrow[i][0] = lrow[i][0] * al0 + sum0;
            lrow[i][1] = lrow[i][1] * al1 + sum1;

            #pragma unroll
            for (int jo = 0; jo < 8; jo++) {
                o[i][jo][0] *= al0; o[i][jo][1] *= al0;
                o[i][jo][2] *= al1; o[i][jo][3] *= al1;
            }
        }

        // ---- O += P @ V : P C-frags -> A-frags via intra-quad shuffles ----
        #pragma unroll
        for (int j = 0; j < 8; j++) {
            uint32_t pa[2][4];
            #pragma unroll
            for (int i = 0; i < 2; i++) {
                float x0A = __shfl_sync(0xffffffffu, s[i][j][0], srcA);
                float x1A = __shfl_sync(0xffffffffu, s[i][j][1], srcA);
                float x0B = __shfl_sync(0xffffffffu, s[i][j][0], srcB);
                float x1B = __shfl_sync(0xffffffffu, s[i][j][1], srcB);
                float y0A = __shfl_sync(0xffffffffu, s[i][j][2], srcA);
                float y1A = __shfl_sync(0xffffffffu, s[i][j][3], srcA);
                float y0B = __shfl_sync(0xffffffffu, s[i][j][2], srcB);
                float y1B = __shfl_sync(0xffffffffu, s[i][j][3], srcB);
                pa[i][0] = to_tf32(e1 ? x1A : x0A);
                pa[i][1] = to_tf32(e1 ? y1A : y0A);
                pa[i][2] = to_tf32(e1 ? x1B : x0B);
                pa[i][3] = to_tf32(e1 ? y1B : y0B);
            }
            #pragma unroll
            for (int jo = 0; jo < 8; jo++) {
                uint32_t bf[2];
                bf[0] = __float_as_uint(Vs[(j * 8 + tg) * KSTR + jo * 8 + g]);
                bf[1] = __float_as_uint(Vs[(j * 8 + tg + 4) * KSTR + jo * 8 + g]);
                mma8(o[0][jo], pa[0], bf);
                mma8(o[1][jo], pa[1], bf);
            }
        }
    }

    // ---- normalize and write out ----
    #pragma unroll
    for (int i = 0; i < 2; i++) {
        float inv0 = 1.0f / lrow[i][0];
        float inv1 = 1.0f / lrow[i][1];
        #pragma unroll
        for (int jo = 0; jo < 8; jo++) {
            int col = h * HDD + jo * 8 + tg * 2;
            *reinterpret_cast<float2*>(
                attn + (size_t)(b * SS + row[i][0]) * DD + col) =
                make_float2(o[i][jo][0] * inv0, o[i][jo][1] * inv0);
            *reinterpret_cast<float2*>(
                attn + (size_t)(b * SS + row[i][1]) * DD + col) =
                make_float2(o[i][jo][2] * inv1, o[i][jo][3] * inv1);
        }
    }
}

// -------------------- fused residual-add + LayerNorm -----------------------
__global__ void add_ln_kernel(const float* __restrict__ x,
                              const float* __restrict__ y,
                              const float* __restrict__ w,
                              const float* __restrict__ b,
                              float* __restrict__ out) {
    int row = blockIdx.x;
    const float* xr = x + (size_t)row * DD;
    const float* yr = y + (size_t)row * DD;
    int tid = threadIdx.x;

    float v0 = xr[tid] + yr[tid];
    float v1 = xr[tid + 256] + yr[tid + 256];
    float v2 = xr[tid + 512] + yr[tid + 512];

    __shared__ float sh[8];
    float s = warp_sum(v0 + v1 + v2);
    if ((tid & 31) == 0) sh[tid >> 5] = s;
    __syncthreads();
    float tot = 0.f;
    #pragma unroll
    for (int i = 0; i < 8; i++) tot += sh[i];
    float mu = tot * (1.0f / DD);
    __syncthreads();

    float d0 = v0 - mu, d1 = v1 - mu, d2 = v2 - mu;
    float s2 = warp_sum(d0 * d0 + d1 * d1 + d2 * d2);
    if ((tid & 31) == 0) sh[tid >> 5] = s2;
    __syncthreads();
    float tot2 = 0.f;
    #pragma unroll
    for (int i = 0; i < 8; i++) tot2 += sh[i];
    float r = rsqrtf(tot2 * (1.0f / DD) + 1e-5f);

    float* orow = out + (size_t)row * DD;
    orow[tid]       = d0 * r * w[tid]       + b[tid];
    orow[tid + 256] = d1 * r * w[tid + 256] + b[tid + 256];
    orow[tid + 512] = d2 * r * w[tid + 512] + b[tid + 512];
}

// ---------------------------------------------------------------------------
extern "C" void kernel_launch(void* const* d_in, const int* in_sizes, int n_in,
                              void* d_out, int out_size) {
    const int*   ids      = (const int*)  d_in[0];
    const float* mask     = (const float*)d_in[2];
    const float* tok_emb  = (const float*)d_in[3];
    const float* pos_emb  = (const float*)d_in[4];
    const float* c_attn_w = (const float*)d_in[5];
    const float* c_attn_b = (const float*)d_in[6];
    const float* c_proj_w = (const float*)d_in[7];
    const float* c_proj_b = (const float*)d_in[8];
    const float* ln1_w    = (const float*)d_in[9];
    const float* ln1_b    = (const float*)d_in[10];
    const float* c_fc_w   = (const float*)d_in[11];
    const float* c_fc_b   = (const float*)d_in[12];
    const float* mlp_w    = (const float*)d_in[13];
    const float* mlp_b    = (const float*)d_in[14];
    const float* ln2_w    = (const float*)d_in[15];
    const float* ln2_b    = (const float*)d_in[16];

    float *h, *n, *tmp, *attn, *qkv, *fc;
    cudaGetSymbolAddress((void**)&h,    g_h);
    cudaGetSymbolAddress((void**)&n,    g_n);
    cudaGetSymbolAddress((void**)&tmp,  g_tmp);
    cudaGetSymbolAddress((void**)&attn, g_attn);
    cudaGetSymbolAddress((void**)&qkv,  g_qkv);
    cudaGetSymbolAddress((void**)&fc,   g_fc);

    const int flashSmem = (64 * QSTR + 2 * 64 * KSTR + 64) * 4;  // 68864 B
    static int s_attr_set = 0;
    if (!s_attr_set) {
        cudaFuncSetAttribute(flash_kernel,
                             cudaFuncAttributeMaxDynamicSharedMemorySize,
                             flashSmem);
        s_attr_set = 1;
    }

    detect_kernel<<<1, 1>>>(ids);
    embed_kernel<<<(TOKENS * DD + 255) / 256, 256>>>(ids, tok_emb, pos_emb, h);

    for (int i = 0; i < NLAYER; i++) {
        // QKV: [4096,768] @ [768,2304]
        mma_gemm<128, 128, 64, 32, 0><<<dim3(D3 / 128, TOKENS / 128), 256>>>(
            h, DD, c_attn_w + (size_t)i * DD * D3, D3,
            c_attn_b + (size_t)i * D3, qkv, D3, DD);

        // fused flash attention -> attn [4096,768]
        flash_kernel<<<dim3(SS / 128, NB * HH), 128, flashSmem>>>(qkv, mask, attn);

        // attn out projection: [4096,768] @ [768,768]
        mma_gemm<128, 128, 64, 32, 0><<<dim3(DD / 128, TOKENS / 128), 256>>>(
            attn, DD, c_proj_w + (size_t)i * DD * DD, DD,
            c_proj_b + (size_t)i * DD, tmp, DD, DD);

        // n = LN(h + attn_proj)
        add_ln_kernel<<<TOKENS, 256>>>(h, tmp, ln1_w + i * DD, ln1_b + i * DD, n);

        // fc = gelu(n @ c_fc_w + b): [4096,768] @ [768,3072]
        mma_gemm<128, 128, 64, 32, 1><<<dim3(D4 / 128, TOKENS / 128), 256>>>(
            n, DD, c_fc_w + (size_t)i * DD * D4, D4,
            c_fc_b + (size_t)i * D4, fc, D4, DD);

        // m = fc @ mlp_w + b: [4096,3072] @ [3072,768]
        mma_gemm<128, 128, 64, 32, 0><<<dim3(DD / 128, TOKENS / 128), 256>>>(
            fc, D4, mlp_w + (size_t)i * D4 * DD, DD,
            mlp_b + (size_t)i * DD, tmp, DD, D4);

        // h = LN(n + m)  (last layer writes straight to d_out)
        float* dst = (i == NLAYER - 1) ? (float*)d_out : h;
        add_ln_kernel<<<TOKENS, 256>>>(n, tmp, ln2_w + i * DD, ln2_b + i * DD, dst);
    }
}